// round 2
// baseline (speedup 1.0000x reference)
#include <cuda_runtime.h>
#include <cuda_bf16.h>

// ---------------------------------------------------------------------------
// y = u @ W^T  with  W = C (I-A)^{-1} B + D   (everything is linear/TI)
//
// Stage 1: solve_kernel   — X = (I-A)^{-1} B  (forward substitution, 1 block;
//                           each thread owns one column of X -> no syncs)
// Stage 2: wk_kernel      — g_Wk[d][o] = sum_s C[o,s] X[s,d] + D[o,d]
// Stage 3: gemm_kernel    — persistent, W in SMEM, u double-buffered via
//                           cp.async, inner loop in packed fma.rn.f32x2
// ---------------------------------------------------------------------------

#define S 128
#define N_ROWS (32 * 8192)          // 262144 tokens
#define TILE_ROWS 128
#define N_TILES (N_ROWS / TILE_ROWS) // 2048
#define SU_LD 132                    // padded floats per sU row (16B-aligned rows, odd-bank column reads)

__device__ float g_X[S * S];   // [s][d]
__device__ float g_Wk[S * S];  // [d][o]  (transposed W, GEMM-ready)

// ---------------- packed fp32x2 helpers (PTX-only FFMA2 path) ----------------
__device__ __forceinline__ unsigned long long pack2(float x) {
    unsigned long long r;
    asm("mov.b64 %0, {%1, %1};" : "=l"(r) : "f"(x));
    return r;
}
__device__ __forceinline__ void ffma2(unsigned long long& d,
                                      unsigned long long a,
                                      unsigned long long b) {
    asm("fma.rn.f32x2 %0, %1, %2, %0;" : "+l"(d) : "l"(a), "l"(b));
}

__device__ __forceinline__ void cpasync16(void* dst_smem, const void* src_gmem) {
    unsigned int d = (unsigned int)__cvta_generic_to_shared(dst_smem);
    asm volatile("cp.async.cg.shared.global [%0], [%1], 16;" :: "r"(d), "l"(src_gmem));
}

// ---------------------------------------------------------------------------
// Stage 1: forward substitution. Column t of X touched only by thread t.
// ---------------------------------------------------------------------------
__global__ void solve_kernel(const float* __restrict__ A, const float* __restrict__ B) {
    extern __shared__ float sm[];
    float* sA = sm;            // [128][128]
    float* sX = sm + S * S;    // [128][128]
    const int t = threadIdx.x; // 0..127

    // stage A into SMEM (coalesced float4)
    for (int idx = t; idx < S * S / 4; idx += blockDim.x)
        ((float4*)sA)[idx] = ((const float4*)A)[idx];
    __syncthreads();

    for (int i = 0; i < S; i++) {
        const float* ar = sA + i * S;
        float a0 = 0.f, a1 = 0.f, a2 = 0.f, a3 = 0.f;
        int j = 0;
        for (; j + 4 <= i; j += 4) {
            a0 += ar[j + 0] * sX[(j + 0) * S + t];
            a1 += ar[j + 1] * sX[(j + 1) * S + t];
            a2 += ar[j + 2] * sX[(j + 2) * S + t];
            a3 += ar[j + 3] * sX[(j + 3) * S + t];
        }
        for (; j < i; j++) a0 += ar[j] * sX[j * S + t];
        float v = (B[i * S + t] + ((a0 + a1) + (a2 + a3))) / (1.0f - ar[i]);
        sX[i * S + t] = v;
        g_X[i * S + t] = v;
    }
}

// ---------------------------------------------------------------------------
// Stage 2: g_Wk[d][o] = sum_s C[o,s] * X[s,d] + D[o,d]
// 128 consecutive threads share d (X load is broadcast), stores coalesced.
// ---------------------------------------------------------------------------
__global__ void wk_kernel(const float* __restrict__ C, const float* __restrict__ D) {
    const int g = blockIdx.x * blockDim.x + threadIdx.x; // 16384 threads
    const int o = g & (S - 1);
    const int d = g >> 7;
    float acc = D[o * S + d];
    #pragma unroll 8
    for (int s = 0; s < S; s++)
        acc += C[o * S + s] * g_X[s * S + d];
    g_Wk[d * S + o] = acc;
}

// ---------------------------------------------------------------------------
// Stage 3: persistent GEMM, y[n,o] = sum_d u[n,d] * g_Wk[d][o]
// 256 threads: tx=tid&15 (col pairs), ty=tid>>4 (rows ty+16*i).
// Each thread: 8 rows x 8 cols = 32 f32x2 accumulators.
// ---------------------------------------------------------------------------
__global__ __launch_bounds__(256, 1)
void gemm_kernel(const float* __restrict__ u, float* __restrict__ y) {
    extern __shared__ float smem[];
    float* sW  = smem;                      // [128][128] = 64 KB, layout [k][o]
    float* sU0 = smem + S * S;              // [128][SU_LD]
    float* sU1 = sU0 + TILE_ROWS * SU_LD;

    const int tid = threadIdx.x;
    const int tx = tid & 15;
    const int ty = tid >> 4;

    // W tile: resident for the whole kernel
    for (int idx = tid; idx < S * S / 4; idx += 256)
        ((float4*)sW)[idx] = ((const float4*)g_Wk)[idx];

    // prologue: prefetch first tile
    int tile = blockIdx.x;
    if (tile < N_TILES) {
        const float4* src = (const float4*)u + (long)tile * TILE_ROWS * 32;
        #pragma unroll
        for (int p = 0; p < 16; p++) {
            int idx = tid + p * 256;
            int row = idx >> 5, c4 = idx & 31;
            cpasync16(&sU0[row * SU_LD + c4 * 4], src + row * 32 + c4);
        }
        asm volatile("cp.async.commit_group;" ::: "memory");
    }

    int pb = 0;
    for (; tile < N_TILES; tile += gridDim.x) {
        float* cur = pb ? sU1 : sU0;
        float* nxt = pb ? sU0 : sU1;
        const int next = tile + gridDim.x;

        if (next < N_TILES) {
            const float4* src = (const float4*)u + (long)next * TILE_ROWS * 32;
            #pragma unroll
            for (int p = 0; p < 16; p++) {
                int idx = tid + p * 256;
                int row = idx >> 5, c4 = idx & 31;
                cpasync16(&nxt[row * SU_LD + c4 * 4], src + row * 32 + c4);
            }
            asm volatile("cp.async.commit_group;" ::: "memory");
            asm volatile("cp.async.wait_group 1;" ::: "memory");
        } else {
            asm volatile("cp.async.wait_group 0;" ::: "memory");
        }
        __syncthreads();   // cur tile (and sW on first pass) visible to all

        unsigned long long acc[8][4];
        #pragma unroll
        for (int i = 0; i < 8; i++)
            #pragma unroll
            for (int jj = 0; jj < 4; jj++) acc[i][jj] = 0ULL;

        #pragma unroll 4
        for (int k = 0; k < S; k++) {
            unsigned long long wv[4];
            const float* wrow = sW + k * S + tx * 2;
            #pragma unroll
            for (int jj = 0; jj < 4; jj++)
                wv[jj] = *(const unsigned long long*)(wrow + jj * 32);
            #pragma unroll
            for (int i = 0; i < 8; i++) {
                unsigned long long av = pack2(cur[(ty + 16 * i) * SU_LD + k]);
                ffma2(acc[i][0], av, wv[0]);
                ffma2(acc[i][1], av, wv[1]);
                ffma2(acc[i][2], av, wv[2]);
                ffma2(acc[i][3], av, wv[3]);
            }
        }

        float* outp = y + (long)tile * TILE_ROWS * S;
        #pragma unroll
        for (int i = 0; i < 8; i++) {
            int r = ty + 16 * i;
            #pragma unroll
            for (int jj = 0; jj < 4; jj++) {
                int c = tx * 2 + jj * 32;
                *(unsigned long long*)(outp + r * S + c) = acc[i][jj];
            }
        }
        __syncthreads();   // done reading cur before it becomes next prefetch target
        pb ^= 1;
    }
}

// ---------------------------------------------------------------------------
extern "C" void kernel_launch(void* const* d_in, const int* in_sizes, int n_in,
                              void* d_out, int out_size) {
    const float* u = (const float*)d_in[0];
    const float* A = (const float*)d_in[1];
    const float* B = (const float*)d_in[2];
    const float* C = (const float*)d_in[3];
    const float* D = (const float*)d_in[4];
    float* y = (float*)d_out;

    static_assert(TILE_ROWS * N_TILES == N_ROWS, "tiling");

    int sms = 0;
    int dev = 0;
    cudaGetDevice(&dev);
    cudaDeviceGetAttribute(&sms, cudaDevAttrMultiProcessorCount, dev);
    if (sms <= 0) sms = 148;

    const int solve_smem = 2 * S * S * (int)sizeof(float);                 // 128 KB
    const int gemm_smem  = (S * S + 2 * TILE_ROWS * SU_LD) * (int)sizeof(float); // 196.5 KB
    cudaFuncSetAttribute(solve_kernel, cudaFuncAttributeMaxDynamicSharedMemorySize, solve_smem);
    cudaFuncSetAttribute(gemm_kernel,  cudaFuncAttributeMaxDynamicSharedMemorySize, gemm_smem);

    solve_kernel<<<1, 128, solve_smem>>>(A, B);
    wk_kernel<<<128, 128>>>(C, D);
    gemm_kernel<<<sms, 256, gemm_smem>>>(u, y);
}

// round 7
// speedup vs baseline: 2.2922x; 2.2922x over previous
#include <cuda_runtime.h>
#include <cuda_bf16.h>
#include <cstdint>

// ===========================================================================
// y = u @ W^T,  W = C (I-A)^{-1} B + D   (model is linear & time-invariant)
//
// Stage 1 solve_kernel : X = (I-A)^{-1} B, warp-per-column forward subst.
// Stage 2 wk_kernel    : W = C X + D, split to bf16 hi/lo, stored as a
//                        swizzled [n][k] image (ldmatrix-ready).
// Stage 3 gemm_kernel  : persistent HMMA (mma.sync bf16) 3-term split GEMM
//                        y = uh*Wh + uh*Wl + ul*Wh   (fp32 accumulate)
// NOTE: tcgen05 is NOT usable here — harness PTX stage targets compute_103
// (no 'a' suffix), which rejects all sm_103a-only instructions.
// ===========================================================================

#define SDIM 128
#define N_ROWS (32 * 8192)            // 262144 tokens
#define N_TILES (N_ROWS / 128)        // 2048 tiles of 128 rows

__device__ float g_X[SDIM * SDIM];                // [s][d]
__device__ __nv_bfloat16 g_Wh[SDIM * SDIM];       // swizzled image, hi
__device__ __nv_bfloat16 g_Wl[SDIM * SDIM];       // swizzled image, lo

__device__ __forceinline__ uint32_t smem_u32(const void* p) {
    return (uint32_t)__cvta_generic_to_shared(p);
}

// Swizzle: [128][128] bf16 tile, row-major, 256B rows. 16B units within a
// row get XORed with (row&7) so ldmatrix's 8-row fetches are conflict-free.
// element index for (row r, col k):
__device__ __forceinline__ int swz_elem(int r, int k) {
    return r * 128 + ((((k >> 3) ^ (r & 7)) << 3) | (k & 7));
}

#define LDSM4(r, a) \
    asm volatile("ldmatrix.sync.aligned.m8n8.x4.shared.b16 {%0,%1,%2,%3}, [%4];" \
        : "=r"((r)[0]), "=r"((r)[1]), "=r"((r)[2]), "=r"((r)[3]) : "r"(a))

#define MMA16816(d, a, b0, b1) \
    asm volatile("mma.sync.aligned.m16n8k16.row.col.f32.bf16.bf16.f32 " \
        "{%0,%1,%2,%3}, {%4,%5,%6,%7}, {%8,%9}, {%0,%1,%2,%3};" \
        : "+f"((d)[0]), "+f"((d)[1]), "+f"((d)[2]), "+f"((d)[3]) \
        : "r"((a)[0]), "r"((a)[1]), "r"((a)[2]), "r"((a)[3]), "r"(b0), "r"(b1))

// ===========================================================================
// Stage 1: forward substitution, warp per column. x in registers:
// lane l holds x_j for j in {l, l+32, l+64, l+96}.
// ===========================================================================
__global__ void solve_kernel(const float* __restrict__ A, const float* __restrict__ B) {
    extern __shared__ float sm1[];
    float* sA    = sm1;               // [128][128]
    float* sBt   = sm1 + SDIM * SDIM; // [16 cols][129]
    float* rdiag = sBt + 16 * 129;    // [128]

    const int tid  = threadIdx.x;     // 512 threads
    const int lane = tid & 31;
    const int w    = tid >> 5;        // 0..15
    const int col  = blockIdx.x * 16 + w;
    const int cbase = blockIdx.x * 16;

    for (int idx = tid; idx < SDIM * SDIM / 4; idx += blockDim.x)
        ((float4*)sA)[idx] = ((const float4*)A)[idx];
    for (int idx = tid; idx < 16 * SDIM; idx += blockDim.x) {
        int cc = idx & 15, i = idx >> 4;
        sBt[cc * 129 + i] = B[i * SDIM + cbase + cc];
    }
    if (tid < SDIM) rdiag[tid] = 1.0f / (1.0f - A[tid * SDIM + tid]);
    __syncthreads();

    float xr[4] = {0.f, 0.f, 0.f, 0.f};
    float br[4], rd[4];
    #pragma unroll
    for (int q = 0; q < 4; q++) {
        br[q] = sBt[w * 129 + lane + 32 * q];
        rd[q] = rdiag[lane + 32 * q];
    }

    for (int i = 0; i < SDIM; i++) {
        const float* ar = sA + i * SDIM;
        float s = 0.f;
        #pragma unroll
        for (int q = 0; q < 4; q++) {
            int j = lane + 32 * q;
            float a = (j < i) ? ar[j] : 0.f;
            s = fmaf(a, xr[q], s);
        }
        #pragma unroll
        for (int m = 16; m > 0; m >>= 1)
            s += __shfl_xor_sync(0xFFFFFFFFu, s, m);
        if (lane == (i & 31)) {
            int q = i >> 5;
            xr[q] = (br[q] + s) * rd[q];
        }
    }
    #pragma unroll
    for (int q = 0; q < 4; q++)
        g_X[(lane + 32 * q) * SDIM + col] = xr[q];
}

// ===========================================================================
// Stage 2: W[o][d] = sum_s C[o,s] X[s,d] + D[o,d]; C row broadcast per block,
// g_X coalesced. Emit bf16 hi/lo into the swizzled ldmatrix image.
// ===========================================================================
__global__ void wk_kernel(const float* __restrict__ C, const float* __restrict__ Dm) {
    const int g = blockIdx.x * blockDim.x + threadIdx.x;  // 16384
    const int o = g >> 7;          // same for whole block -> C row broadcast
    const int d = g & (SDIM - 1);  // consecutive -> coalesced X reads
    float acc = Dm[o * SDIM + d];
    #pragma unroll 8
    for (int s = 0; s < SDIM; s++)
        acc = fmaf(C[o * SDIM + s], g_X[s * SDIM + d], acc);
    __nv_bfloat16 h = __float2bfloat16(acc);
    __nv_bfloat16 l = __float2bfloat16(acc - __bfloat162float(h));
    int idx = swz_elem(o, d);
    g_Wh[idx] = h;
    g_Wl[idx] = l;
}

// ===========================================================================
// Stage 3: persistent HMMA GEMM. SMEM: [0,32K) Wh  [32K,64K) Wl
//                                      [64K,96K) Uh [96K,128K) Ul
// 8 warps = 4 row-groups x 2 col-halves; warp tile 32 rows x 64 cols.
// ===========================================================================
#define GSMEM_BYTES (128 * 1024)

__global__ __launch_bounds__(256, 1)
void gemm_kernel(const float* __restrict__ u, float* __restrict__ y, int grid) {
    extern __shared__ __align__(16) unsigned char sm[];
    const uint32_t sbase = smem_u32(sm);

    const int tid  = threadIdx.x;
    const int lane = tid & 31;
    const int w    = tid >> 5;
    const int rg   = w >> 1;           // row-group 0..3
    const int cw   = w & 1;            // col half 0..1
    const int Rw   = rg * 32;

    // W images -> SMEM (already swizzled; linear copy)
    {
        const uint4* sh = (const uint4*)g_Wh;
        const uint4* sl = (const uint4*)g_Wl;
        uint4* dh = (uint4*)sm;
        uint4* dl = (uint4*)(sm + 32768);
        for (int i = tid; i < 2048; i += 256) { dh[i] = sh[i]; dl[i] = sl[i]; }
    }

    // prefetch first tile into registers
    float4 v[16];
    int tile = blockIdx.x;
    if (tile < N_TILES) {
        const float4* src = (const float4*)u + (long)tile * 4096;
        #pragma unroll
        for (int j = 0; j < 8; j++) {
            int uid = tid + 256 * j;
            v[2 * j]     = src[uid * 2];
            v[2 * j + 1] = src[uid * 2 + 1];
        }
    }
    __syncthreads();

    // ldmatrix lane geometry (low-3 row bits == lane&7 for all fetches)
    const int a_row  = Rw + (lane & 7) + ((lane >> 3) & 1) * 8;  // A: frag rows
    const int a_kadd = ((lane >> 4) & 1) * 8;
    const int b_n    = cw * 64 + (lane & 7) + ((lane >> 4) & 1) * 8;
    const int b_kadd = ((lane >> 3) & 1) * 8;
    const int r7     = lane & 7;

    for (; tile < N_TILES; tile += grid) {
        // ---- convert prefetched fp32 -> bf16 hi/lo, store swizzled --------
        #pragma unroll
        for (int j = 0; j < 8; j++) {
            int uid = tid + 256 * j;
            int row = uid >> 4, kk = (uid & 15);   // kk = 16B unit in row
            float4 p0 = v[2 * j], p1 = v[2 * j + 1];
            __nv_bfloat162 h01 = __floats2bfloat162_rn(p0.x, p0.y);
            __nv_bfloat162 h23 = __floats2bfloat162_rn(p0.z, p0.w);
            __nv_bfloat162 h45 = __floats2bfloat162_rn(p1.x, p1.y);
            __nv_bfloat162 h67 = __floats2bfloat162_rn(p1.z, p1.w);
            __nv_bfloat162 l01 = __floats2bfloat162_rn(p0.x - __bfloat162float(h01.x),
                                                       p0.y - __bfloat162float(h01.y));
            __nv_bfloat162 l23 = __floats2bfloat162_rn(p0.z - __bfloat162float(h23.x),
                                                       p0.w - __bfloat162float(h23.y));
            __nv_bfloat162 l45 = __floats2bfloat162_rn(p1.x - __bfloat162float(h45.x),
                                                       p1.y - __bfloat162float(h45.y));
            __nv_bfloat162 l67 = __floats2bfloat162_rn(p1.z - __bfloat162float(h67.x),
                                                       p1.w - __bfloat162float(h67.y));
            int off = row * 256 + ((kk ^ (row & 7)) << 4);   // swizzled 16B unit
            *(uint4*)(sm + 65536 + off) =
                make_uint4(*(uint32_t*)&h01, *(uint32_t*)&h23,
                           *(uint32_t*)&h45, *(uint32_t*)&h67);
            *(uint4*)(sm + 98304 + off) =
                make_uint4(*(uint32_t*)&l01, *(uint32_t*)&l23,
                           *(uint32_t*)&l45, *(uint32_t*)&l67);
        }
        __syncthreads();

        // ---- issue LDG for next tile (latency hidden under MMA) -----------
        const int next = tile + grid;
        if (next < N_TILES) {
            const float4* src = (const float4*)u + (long)next * 4096;
            #pragma unroll
            for (int j = 0; j < 8; j++) {
                int uid = tid + 256 * j;
                v[2 * j]     = src[uid * 2];
                v[2 * j + 1] = src[uid * 2 + 1];
            }
        }

        // ---- MMA mainloop -------------------------------------------------
        float acc[2][8][4];
        #pragma unroll
        for (int rf = 0; rf < 2; rf++)
            #pragma unroll
            for (int nt = 0; nt < 8; nt++)
                #pragma unroll
                for (int q = 0; q < 4; q++) acc[rf][nt][q] = 0.f;

        #pragma unroll
        for (int ks = 0; ks < 8; ks++) {
            const int k0 = ks * 16;
            uint32_t ah0[4], ah1[4], al0[4], al1[4];
            {
                int mk = k0 + a_kadd;
                uint32_t ad = sbase + 65536u +
                    (uint32_t)(a_row * 256 + (((mk >> 3) ^ r7) << 4));
                LDSM4(ah0, ad);
                LDSM4(ah1, ad + 4096u);          // +16 rows
                LDSM4(al0, ad + 32768u);
                LDSM4(al1, ad + 36864u);
            }
            #pragma unroll
            for (int cg = 0; cg < 4; cg++) {
                int n = b_n + cg * 16;
                int mk = k0 + b_kadd;
                uint32_t bd = sbase +
                    (uint32_t)(n * 256 + (((mk >> 3) ^ r7) << 4));
                uint32_t bh[4], bl[4];
                LDSM4(bh, bd);
                LDSM4(bl, bd + 32768u);
                const int nt = cg * 2;
                MMA16816(acc[0][nt],     ah0, bh[0], bh[1]);
                MMA16816(acc[0][nt + 1], ah0, bh[2], bh[3]);
                MMA16816(acc[1][nt],     ah1, bh[0], bh[1]);
                MMA16816(acc[1][nt + 1], ah1, bh[2], bh[3]);
                MMA16816(acc[0][nt],     ah0, bl[0], bl[1]);
                MMA16816(acc[0][nt + 1], ah0, bl[2], bl[3]);
                MMA16816(acc[1][nt],     ah1, bl[0], bl[1]);
                MMA16816(acc[1][nt + 1], ah1, bl[2], bl[3]);
                MMA16816(acc[0][nt],     al0, bh[0], bh[1]);
                MMA16816(acc[0][nt + 1], al0, bh[2], bh[3]);
                MMA16816(acc[1][nt],     al1, bh[0], bh[1]);
                MMA16816(acc[1][nt + 1], al1, bh[2], bh[3]);
            }
        }

        // ---- epilogue: fragments -> y (fire-and-forget STG) ---------------
        {
            const int q = lane >> 2, s2 = (lane & 3) * 2;
            #pragma unroll
            for (int rf = 0; rf < 2; rf++) {
                long grow = (long)tile * 128 + Rw + rf * 16 + q;
                float* yp0 = y + grow * SDIM + cw * 64 + s2;
                #pragma unroll
                for (int nt = 0; nt < 8; nt++) {
                    *(float2*)(yp0 + nt * 8) =
                        make_float2(acc[rf][nt][0], acc[rf][nt][1]);
                    *(float2*)(yp0 + 8 * SDIM + nt * 8) =
                        make_float2(acc[rf][nt][2], acc[rf][nt][3]);
                }
            }
        }
        __syncthreads();   // all warps done reading U buffer before next STS
    }
}

// ===========================================================================
extern "C" void kernel_launch(void* const* d_in, const int* in_sizes, int n_in,
                              void* d_out, int out_size) {
    const float* u = (const float*)d_in[0];
    const float* A = (const float*)d_in[1];
    const float* B = (const float*)d_in[2];
    const float* C = (const float*)d_in[3];
    const float* D = (const float*)d_in[4];
    float* y = (float*)d_out;

    int sms = 0, dev = 0;
    cudaGetDevice(&dev);
    cudaDeviceGetAttribute(&sms, cudaDevAttrMultiProcessorCount, dev);
    if (sms <= 0) sms = 148;

    const int solve_smem = (SDIM * SDIM + 16 * 129 + SDIM) * (int)sizeof(float);
    cudaFuncSetAttribute(solve_kernel, cudaFuncAttributeMaxDynamicSharedMemorySize, solve_smem);
    cudaFuncSetAttribute(gemm_kernel,  cudaFuncAttributeMaxDynamicSharedMemorySize, GSMEM_BYTES);

    solve_kernel<<<8, 512, solve_smem>>>(A, B);
    wk_kernel<<<128, 128>>>(C, D);
    gemm_kernel<<<sms, 256, GSMEM_BYTES>>>(u, y, sms);
}

// round 8
// speedup vs baseline: 2.8179x; 1.2293x over previous
#include <cuda_runtime.h>
#include <cuda_bf16.h>
#include <cstdint>

// ===========================================================================
// y = u @ W^T,  W = C (I-A)^{-1} B + D   (model is linear & time-invariant)
//
// Stage 1 solve_kernel : X = (I-A)^{-1} B, single-block BLOCKED forward
//                        substitution (GEMM rhs-updates + register-chain
//                        32x32 diagonal solves; no shuffles).
// Stage 2 wk_kernel    : W = C X + D -> bf16 hi/lo swizzled ldmatrix image.
// Stage 3 gemm_kernel  : persistent HMMA 3-term split GEMM, double-buffered
//                        U, ONE sync/tile, convert/STS interleaved into the
//                        MMA ks-loop so LSU/ALU work fills tensor-idle slots.
// NOTE: tcgen05 unusable (harness PTX targets compute_103, no 'a').
// ===========================================================================

#define SDIM 128
#define N_ROWS (32 * 8192)
#define N_TILES (N_ROWS / 128)        // 2048

__device__ float g_X[SDIM * SDIM];
__device__ __nv_bfloat16 g_Wh[SDIM * SDIM];
__device__ __nv_bfloat16 g_Wl[SDIM * SDIM];

__device__ __forceinline__ uint32_t smem_u32(const void* p) {
    return (uint32_t)__cvta_generic_to_shared(p);
}
__device__ __forceinline__ int swz_elem(int r, int k) {
    return r * 128 + ((((k >> 3) ^ (r & 7)) << 3) | (k & 7));
}

#define LDSM4(r, a) \
    asm volatile("ldmatrix.sync.aligned.m8n8.x4.shared.b16 {%0,%1,%2,%3}, [%4];" \
        : "=r"((r)[0]), "=r"((r)[1]), "=r"((r)[2]), "=r"((r)[3]) : "r"(a))

#define MMA16816(d, a, b0, b1) \
    asm volatile("mma.sync.aligned.m16n8k16.row.col.f32.bf16.bf16.f32 " \
        "{%0,%1,%2,%3}, {%4,%5,%6,%7}, {%8,%9}, {%0,%1,%2,%3};" \
        : "+f"((d)[0]), "+f"((d)[1]), "+f"((d)[2]), "+f"((d)[3]) \
        : "r"((a)[0]), "r"((a)[1]), "r"((a)[2]), "r"((a)[3]), "r"(b0), "r"(b1))

// ===========================================================================
// Stage 1: blocked forward substitution, ONE block / 1024 threads.
// (I-A)X = B. Block rows of 32: rhs_I = B_I + sum_{J<I} A_IJ X_J (GEMM),
// then T_II X_I = rhs_I solved column-per-thread with acc-forward registers.
// ===========================================================================
__global__ __launch_bounds__(1024, 1)
void solve_kernel(const float* __restrict__ A, const float* __restrict__ B) {
    extern __shared__ float sm1[];
    float* sA    = sm1;           // [128][128]
    float* sX    = sm1 + 16384;   // [128][128], init = B, becomes X
    float* rdiag = sX + 16384;    // [128]

    const int tid = threadIdx.x;

    for (int i = tid; i < 4096; i += 1024) {
        ((float4*)sA)[i] = ((const float4*)A)[i];
        ((float4*)sX)[i] = ((const float4*)B)[i];
    }
    __syncthreads();
    if (tid < 128) rdiag[tid] = 1.0f / (1.0f - sA[tid * 128 + tid]);
    __syncthreads();

    // update-phase mapping: 256 threads, 4 rows x 4 cols each
    const int rp = tid >> 5;      // 0..7 (row group of 4)
    const int cg = tid & 31;      // float4 column group

    for (int I = 0; I < 4; I++) {
        const int r0 = I * 32;
        if (I > 0 && tid < 256) {
            float4 acc0 = {0,0,0,0}, acc1 = {0,0,0,0},
                   acc2 = {0,0,0,0}, acc3 = {0,0,0,0};
            const float* a0 = sA + (r0 + rp * 4 + 0) * 128;
            const float* a1 = sA + (r0 + rp * 4 + 1) * 128;
            const float* a2 = sA + (r0 + rp * 4 + 2) * 128;
            const float* a3 = sA + (r0 + rp * 4 + 3) * 128;
            #pragma unroll 4
            for (int j = 0; j < r0; j++) {
                float4 xv = *(float4*)(sX + j * 128 + 4 * cg);
                float b0 = a0[j], b1 = a1[j], b2 = a2[j], b3 = a3[j];
                acc0.x = fmaf(b0, xv.x, acc0.x); acc0.y = fmaf(b0, xv.y, acc0.y);
                acc0.z = fmaf(b0, xv.z, acc0.z); acc0.w = fmaf(b0, xv.w, acc0.w);
                acc1.x = fmaf(b1, xv.x, acc1.x); acc1.y = fmaf(b1, xv.y, acc1.y);
                acc1.z = fmaf(b1, xv.z, acc1.z); acc1.w = fmaf(b1, xv.w, acc1.w);
                acc2.x = fmaf(b2, xv.x, acc2.x); acc2.y = fmaf(b2, xv.y, acc2.y);
                acc2.z = fmaf(b2, xv.z, acc2.z); acc2.w = fmaf(b2, xv.w, acc2.w);
                acc3.x = fmaf(b3, xv.x, acc3.x); acc3.y = fmaf(b3, xv.y, acc3.y);
                acc3.z = fmaf(b3, xv.z, acc3.z); acc3.w = fmaf(b3, xv.w, acc3.w);
            }
            #pragma unroll
            for (int r = 0; r < 4; r++) {
                float4 av = (r == 0) ? acc0 : (r == 1) ? acc1 : (r == 2) ? acc2 : acc3;
                float4* dst = (float4*)(sX + (r0 + rp * 4 + r) * 128 + 4 * cg);
                float4 c = *dst;
                c.x += av.x; c.y += av.y; c.z += av.z; c.w += av.w;
                *dst = c;
            }
        }
        __syncthreads();
        if (tid < 128) {
            float xv[32], ac[32];
            #pragma unroll
            for (int q = 0; q < 32; q++) ac[q] = 0.f;
            #pragma unroll
            for (int j = 0; j < 32; j++) {
                float xj = (sX[(r0 + j) * 128 + tid] + ac[j]) * rdiag[r0 + j];
                xv[j] = xj;
                #pragma unroll
                for (int i2 = j + 1; i2 < 32; i2++)
                    ac[i2] = fmaf(sA[(r0 + i2) * 128 + r0 + j], xj, ac[i2]);
            }
            #pragma unroll
            for (int j = 0; j < 32; j++) sX[(r0 + j) * 128 + tid] = xv[j];
        }
        __syncthreads();
    }

    for (int i = tid; i < 4096; i += 1024)
        ((float4*)g_X)[i] = ((const float4*)sX)[i];
}

// ===========================================================================
// Stage 2: W[o][d] = sum_s C[o,s] X[s,d] + D[o,d] -> swizzled bf16 hi/lo
// ===========================================================================
__global__ void wk_kernel(const float* __restrict__ C, const float* __restrict__ Dm) {
    const int g = blockIdx.x * blockDim.x + threadIdx.x;
    const int o = g >> 7;
    const int d = g & (SDIM - 1);
    float acc = Dm[o * SDIM + d];
    #pragma unroll 8
    for (int s = 0; s < SDIM; s++)
        acc = fmaf(C[o * SDIM + s], g_X[s * SDIM + d], acc);
    __nv_bfloat16 h = __float2bfloat16(acc);
    __nv_bfloat16 l = __float2bfloat16(acc - __bfloat162float(h));
    int idx = swz_elem(o, d);
    g_Wh[idx] = h;
    g_Wl[idx] = l;
}

// ===========================================================================
// Stage 3: persistent HMMA GEMM.
// SMEM: [0,32K) Wh | [32K,64K) Wl | buf p at 64K + p*64K: Uh(32K)+Ul(32K)
// ===========================================================================
#define GSMEM_BYTES (192 * 1024)
#define UBOFF(p) (65536u + (uint32_t)(p) * 65536u)

__global__ __launch_bounds__(256, 1)
void gemm_kernel(const float* __restrict__ u, float* __restrict__ y, int grid) {
    extern __shared__ __align__(16) unsigned char sm[];
    const uint32_t sbase = smem_u32(sm);

    const int tid  = threadIdx.x;
    const int lane = tid & 31;
    const int w    = tid >> 5;
    const int rg   = w >> 1;
    const int cw   = w & 1;
    const int Rw   = rg * 32;

    // W images -> SMEM
    {
        const uint4* sh = (const uint4*)g_Wh;
        const uint4* sl = (const uint4*)g_Wl;
        uint4* dh = (uint4*)sm;
        uint4* dl = (uint4*)(sm + 32768);
        for (int i = tid; i < 2048; i += 256) { dh[i] = sh[i]; dl[i] = sl[i]; }
    }

    const int a_row  = Rw + (lane & 7) + ((lane >> 3) & 1) * 8;
    const int a_kadd = ((lane >> 4) & 1) * 8;
    const int b_n    = cw * 64 + (lane & 7) + ((lane >> 4) & 1) * 8;
    const int b_kadd = ((lane >> 3) & 1) * 8;
    const int r7     = lane & 7;

    float4 v[16];
    int tile = blockIdx.x;

    // ---- prologue: tile0 -> buf0; prefetch tile1 into regs ---------------
    if (tile < N_TILES) {
        const float4* src = (const float4*)u + (long)tile * 4096;
        #pragma unroll
        for (int j = 0; j < 8; j++) {
            int uid = tid + 256 * j;
            v[2 * j]     = src[uid * 2];
            v[2 * j + 1] = src[uid * 2 + 1];
        }
        #pragma unroll
        for (int j = 0; j < 8; j++) {
            int uid = tid + 256 * j;
            int row = uid >> 4, kk = uid & 15;
            float4 p0 = v[2 * j], p1 = v[2 * j + 1];
            __nv_bfloat162 h01 = __floats2bfloat162_rn(p0.x, p0.y);
            __nv_bfloat162 h23 = __floats2bfloat162_rn(p0.z, p0.w);
            __nv_bfloat162 h45 = __floats2bfloat162_rn(p1.x, p1.y);
            __nv_bfloat162 h67 = __floats2bfloat162_rn(p1.z, p1.w);
            __nv_bfloat162 l01 = __floats2bfloat162_rn(p0.x - __bfloat162float(h01.x),
                                                       p0.y - __bfloat162float(h01.y));
            __nv_bfloat162 l23 = __floats2bfloat162_rn(p0.z - __bfloat162float(h23.x),
                                                       p0.w - __bfloat162float(h23.y));
            __nv_bfloat162 l45 = __floats2bfloat162_rn(p1.x - __bfloat162float(h45.x),
                                                       p1.y - __bfloat162float(h45.y));
            __nv_bfloat162 l67 = __floats2bfloat162_rn(p1.z - __bfloat162float(h67.x),
                                                       p1.w - __bfloat162float(h67.y));
            int off = row * 256 + ((kk ^ (row & 7)) << 4);
            *(uint4*)(sm + UBOFF(0) + off) =
                make_uint4(*(uint32_t*)&h01, *(uint32_t*)&h23,
                           *(uint32_t*)&h45, *(uint32_t*)&h67);
            *(uint4*)(sm + UBOFF(0) + 32768 + off) =
                make_uint4(*(uint32_t*)&l01, *(uint32_t*)&l23,
                           *(uint32_t*)&l45, *(uint32_t*)&l67);
        }
    }
    if (tile + grid < N_TILES) {
        const float4* src = (const float4*)u + (long)(tile + grid) * 4096;
        #pragma unroll
        for (int j = 0; j < 8; j++) {
            int uid = tid + 256 * j;
            v[2 * j]     = src[uid * 2];
            v[2 * j + 1] = src[uid * 2 + 1];
        }
    }
    __syncthreads();

    int p = 0;
    for (; tile < N_TILES; tile += grid) {
        const bool hasNext = (tile + grid) < N_TILES;
        const uint32_t ub  = UBOFF(p);
        const uint32_t ubn = UBOFF(p ^ 1);

        float acc[2][8][4];
        #pragma unroll
        for (int rf = 0; rf < 2; rf++)
            #pragma unroll
            for (int nt = 0; nt < 8; nt++)
                #pragma unroll
                for (int q = 0; q < 4; q++) acc[rf][nt][q] = 0.f;

        #pragma unroll
        for (int ks = 0; ks < 8; ks++) {
            const int k0 = ks * 16;
            uint32_t ah0[4], ah1[4], al0[4], al1[4];
            {
                int mk = k0 + a_kadd;
                uint32_t ad = sbase + ub +
                    (uint32_t)(a_row * 256 + (((mk >> 3) ^ r7) << 4));
                LDSM4(ah0, ad);
                LDSM4(ah1, ad + 4096u);
                LDSM4(al0, ad + 32768u);
                LDSM4(al1, ad + 36864u);
            }
            #pragma unroll
            for (int cg2 = 0; cg2 < 4; cg2++) {
                int n = b_n + cg2 * 16;
                int mk = k0 + b_kadd;
                uint32_t bd = sbase +
                    (uint32_t)(n * 256 + (((mk >> 3) ^ r7) << 4));
                uint32_t bh[4], bl[4];
                LDSM4(bh, bd);
                LDSM4(bl, bd + 32768u);
                const int nt = cg2 * 2;
                MMA16816(acc[0][nt],     ah0, bh[0], bh[1]);
                MMA16816(acc[0][nt + 1], ah0, bh[2], bh[3]);
                MMA16816(acc[1][nt],     ah1, bh[0], bh[1]);
                MMA16816(acc[1][nt + 1], ah1, bh[2], bh[3]);
                MMA16816(acc[0][nt],     ah0, bl[0], bl[1]);
                MMA16816(acc[0][nt + 1], ah0, bl[2], bl[3]);
                MMA16816(acc[1][nt],     ah1, bl[0], bl[1]);
                MMA16816(acc[1][nt + 1], ah1, bl[2], bl[3]);
                MMA16816(acc[0][nt],     al0, bh[0], bh[1]);
                MMA16816(acc[0][nt + 1], al0, bh[2], bh[3]);
                MMA16816(acc[1][nt],     al1, bh[0], bh[1]);
                MMA16816(acc[1][nt + 1], al1, bh[2], bh[3]);
            }
            // interleave next-tile convert/STS chunk: fills tensor-idle slots
            if (hasNext) {
                int uid = tid + 256 * ks;
                int row = uid >> 4, kk = uid & 15;
                float4 p0 = v[2 * ks], p1 = v[2 * ks + 1];
                __nv_bfloat162 h01 = __floats2bfloat162_rn(p0.x, p0.y);
                __nv_bfloat162 h23 = __floats2bfloat162_rn(p0.z, p0.w);
                __nv_bfloat162 h45 = __floats2bfloat162_rn(p1.x, p1.y);
                __nv_bfloat162 h67 = __floats2bfloat162_rn(p1.z, p1.w);
                __nv_bfloat162 l01 = __floats2bfloat162_rn(p0.x - __bfloat162float(h01.x),
                                                           p0.y - __bfloat162float(h01.y));
                __nv_bfloat162 l23 = __floats2bfloat162_rn(p0.z - __bfloat162float(h23.x),
                                                           p0.w - __bfloat162float(h23.y));
                __nv_bfloat162 l45 = __floats2bfloat162_rn(p1.x - __bfloat162float(h45.x),
                                                           p1.y - __bfloat162float(h45.y));
                __nv_bfloat162 l67 = __floats2bfloat162_rn(p1.z - __bfloat162float(h67.x),
                                                           p1.w - __bfloat162float(h67.y));
                int off = row * 256 + ((kk ^ (row & 7)) << 4);
                *(uint4*)(sm + ubn + off) =
                    make_uint4(*(uint32_t*)&h01, *(uint32_t*)&h23,
                               *(uint32_t*)&h45, *(uint32_t*)&h67);
                *(uint4*)(sm + ubn + 32768 + off) =
                    make_uint4(*(uint32_t*)&l01, *(uint32_t*)&l23,
                               *(uint32_t*)&l45, *(uint32_t*)&l67);
            }
        }

        // epilogue: fragments -> y
        {
            const int q = lane >> 2, s2 = (lane & 3) * 2;
            #pragma unroll
            for (int rf = 0; rf < 2; rf++) {
                long grow = (long)tile * 128 + Rw + rf * 16 + q;
                float* yp0 = y + grow * SDIM + cw * 64 + s2;
                #pragma unroll
                for (int nt = 0; nt < 8; nt++) {
                    *(float2*)(yp0 + nt * 8) =
                        make_float2(acc[rf][nt][0], acc[rf][nt][1]);
                    *(float2*)(yp0 + 8 * SDIM + nt * 8) =
                        make_float2(acc[rf][nt][2], acc[rf][nt][3]);
                }
            }
        }

        // prefetch tile t+2 into regs (v consumed by this iteration's chunks)
        if (tile + 2 * grid < N_TILES) {
            const float4* src = (const float4*)u + (long)(tile + 2 * grid) * 4096;
            #pragma unroll
            for (int j = 0; j < 8; j++) {
                int uid = tid + 256 * j;
                v[2 * j]     = src[uid * 2];
                v[2 * j + 1] = src[uid * 2 + 1];
            }
        }
        __syncthreads();
        p ^= 1;
    }
}

// ===========================================================================
extern "C" void kernel_launch(void* const* d_in, const int* in_sizes, int n_in,
                              void* d_out, int out_size) {
    const float* u = (const float*)d_in[0];
    const float* A = (const float*)d_in[1];
    const float* B = (const float*)d_in[2];
    const float* C = (const float*)d_in[3];
    const float* D = (const float*)d_in[4];
    float* y = (float*)d_out;

    int sms = 0, dev = 0;
    cudaGetDevice(&dev);
    cudaDeviceGetAttribute(&sms, cudaDevAttrMultiProcessorCount, dev);
    if (sms <= 0) sms = 148;

    const int solve_smem = (16384 + 16384 + 128) * (int)sizeof(float);
    cudaFuncSetAttribute(solve_kernel, cudaFuncAttributeMaxDynamicSharedMemorySize, solve_smem);
    cudaFuncSetAttribute(gemm_kernel,  cudaFuncAttributeMaxDynamicSharedMemorySize, GSMEM_BYTES);

    solve_kernel<<<1, 1024, solve_smem>>>(A, B);
    wk_kernel<<<128, 128>>>(C, D);
    gemm_kernel<<<sms, 256, GSMEM_BYTES>>>(u, y, sms);
}

// round 9
// speedup vs baseline: 3.0039x; 1.0660x over previous
#include <cuda_runtime.h>
#include <cuda_fp16.h>
#include <cstdint>

// ===========================================================================
// y = u @ W^T,  W = C (I-A)^{-1} B + D   (model is linear & time-invariant)
//
// Stage 1 solve_kernel : X = (I-A)^{-1} B, 4 blocks x 32 columns, blocked
//                        forward substitution (full-thread GEMM updates +
//                        register-chain 32x32 diagonal solves).
// Stage 2 wk_kernel    : W = C X + D, scaled by 2^6, split fp16 hi/lo,
//                        swizzled ldmatrix images.
// Stage 3 gemm_kernel  : persistent HMMA fp16 2-term GEMM
//                        y = (uh*Wh + uh*Wl) * 2^-6  (fp32 accumulate).
//                        Single fp16 u image (u fp16-rounding ~2^-12 is the
//                        only dropped term -> rel_err ~1e-4 << 1e-3).
// NOTE: tcgen05 unusable (harness PTX targets compute_103, no 'a').
// ===========================================================================

#define SDIM 128
#define N_ROWS (32 * 8192)
#define N_TILES (N_ROWS / 128)        // 2048
#define WSCALE 64.0f
#define WSCALE_INV 0.015625f

__device__ float g_X[SDIM * SDIM];
__device__ __half g_Wh[SDIM * SDIM];   // swizzled image, hi (scaled by 2^6)
__device__ __half g_Wl[SDIM * SDIM];   // swizzled image, lo (scaled by 2^6)

__device__ __forceinline__ uint32_t smem_u32(const void* p) {
    return (uint32_t)__cvta_generic_to_shared(p);
}
__device__ __forceinline__ int swz_elem(int r, int k) {
    return r * 128 + ((((k >> 3) ^ (r & 7)) << 3) | (k & 7));
}

#define LDSM4(r, a) \
    asm volatile("ldmatrix.sync.aligned.m8n8.x4.shared.b16 {%0,%1,%2,%3}, [%4];" \
        : "=r"((r)[0]), "=r"((r)[1]), "=r"((r)[2]), "=r"((r)[3]) : "r"(a))

#define MMA16816H(d, a, b0, b1) \
    asm volatile("mma.sync.aligned.m16n8k16.row.col.f32.f16.f16.f32 " \
        "{%0,%1,%2,%3}, {%4,%5,%6,%7}, {%8,%9}, {%0,%1,%2,%3};" \
        : "+f"((d)[0]), "+f"((d)[1]), "+f"((d)[2]), "+f"((d)[3]) \
        : "r"((a)[0]), "r"((a)[1]), "r"((a)[2]), "r"((a)[3]), "r"(b0), "r"(b1))

// ===========================================================================
// Stage 1: blocked forward substitution. 4 blocks, 32 columns each.
// ===========================================================================
__global__ __launch_bounds__(256, 1)
void solve_kernel(const float* __restrict__ A, const float* __restrict__ B) {
    extern __shared__ float sm1[];
    float* sA    = sm1;            // [128][128]
    float* sXs   = sm1 + 16384;    // [128][32]  rhs -> X slice
    float* rdiag = sXs + 4096;     // [128]

    const int tid   = threadIdx.x;
    const int cbase = blockIdx.x * 32;

    for (int i = tid; i < 4096; i += 256)
        ((float4*)sA)[i] = ((const float4*)A)[i];
    for (int idx = tid; idx < 4096; idx += 256) {
        int i = idx >> 5, c = idx & 31;
        sXs[idx] = B[i * SDIM + cbase + c];
    }
    __syncthreads();
    if (tid < 128) rdiag[tid] = 1.0f / (1.0f - sA[tid * 129]);
    __syncthreads();

    const int urow = tid >> 3;      // 0..31
    const int ucg  = tid & 7;       // float4 group over 32 cols

    for (int I = 0; I < 4; I++) {
        const int r0 = I * 32;
        if (I > 0) {
            const int row = r0 + urow;
            const float* ar = sA + row * SDIM;
            float4 acc = {0.f, 0.f, 0.f, 0.f};
            #pragma unroll 4
            for (int j = 0; j < r0; j++) {
                float a = ar[j];
                float4 xv = ((float4*)(sXs + j * 32))[ucg];
                acc.x = fmaf(a, xv.x, acc.x);
                acc.y = fmaf(a, xv.y, acc.y);
                acc.z = fmaf(a, xv.z, acc.z);
                acc.w = fmaf(a, xv.w, acc.w);
            }
            float4* dst = (float4*)(sXs + row * 32) + ucg;
            float4 cur = *dst;
            cur.x += acc.x; cur.y += acc.y; cur.z += acc.z; cur.w += acc.w;
            *dst = cur;
        }
        __syncthreads();
        if (tid < 32) {
            const int c = tid;
            float v[32];
            #pragma unroll
            for (int j = 0; j < 32; j++) v[j] = sXs[(r0 + j) * 32 + c];
            #pragma unroll
            for (int j = 0; j < 32; j++) {
                float x = v[j] * rdiag[r0 + j];
                v[j] = x;
                #pragma unroll
                for (int i2 = j + 1; i2 < 32; i2++)
                    v[i2] = fmaf(sA[(r0 + i2) * SDIM + r0 + j], x, v[i2]);
            }
            #pragma unroll
            for (int j = 0; j < 32; j++) sXs[(r0 + j) * 32 + c] = v[j];
        }
        __syncthreads();
    }

    for (int idx = tid; idx < 4096; idx += 256) {
        int i = idx >> 5, c = idx & 31;
        g_X[i * SDIM + cbase + c] = sXs[idx];
    }
}

// ===========================================================================
// Stage 2: W[o][d] = (sum_s C[o,s] X[s,d] + D[o,d]) * 2^6 -> fp16 hi/lo
// ===========================================================================
__global__ void wk_kernel(const float* __restrict__ C, const float* __restrict__ Dm) {
    const int g = blockIdx.x * blockDim.x + threadIdx.x;
    const int o = g >> 7;
    const int d = g & (SDIM - 1);
    float acc = Dm[o * SDIM + d];
    #pragma unroll 8
    for (int s = 0; s < SDIM; s++)
        acc = fmaf(C[o * SDIM + s], g_X[s * SDIM + d], acc);
    float ws = acc * WSCALE;
    __half h = __float2half_rn(ws);
    __half l = __float2half_rn(ws - __half2float(h));
    int idx = swz_elem(o, d);
    g_Wh[idx] = h;
    g_Wl[idx] = l;
}

// ===========================================================================
// Stage 3: persistent HMMA GEMM.
// SMEM: [0,32K) Wh | [32K,64K) Wl | buf p at 64K + p*32K: Uh(32K)
// ===========================================================================
#define GSMEM_BYTES (128 * 1024)
#define UBOFF(p) (65536u + (uint32_t)(p) * 32768u)

__global__ __launch_bounds__(256, 1)
void gemm_kernel(const float* __restrict__ u, float* __restrict__ y, int grid) {
    extern __shared__ __align__(16) unsigned char sm[];
    const uint32_t sbase = smem_u32(sm);

    const int tid  = threadIdx.x;
    const int lane = tid & 31;
    const int w    = tid >> 5;
    const int rg   = w >> 1;
    const int cw   = w & 1;
    const int Rw   = rg * 32;

    // W images -> SMEM
    {
        const uint4* sh = (const uint4*)g_Wh;
        const uint4* sl = (const uint4*)g_Wl;
        uint4* dh = (uint4*)sm;
        uint4* dl = (uint4*)(sm + 32768);
        for (int i = tid; i < 2048; i += 256) { dh[i] = sh[i]; dl[i] = sl[i]; }
    }

    const int a_row  = Rw + (lane & 7) + ((lane >> 3) & 1) * 8;
    const int a_kadd = ((lane >> 4) & 1) * 8;
    const int b_n    = cw * 64 + (lane & 7) + ((lane >> 4) & 1) * 8;
    const int b_kadd = ((lane >> 3) & 1) * 8;
    const int r7     = lane & 7;

    float4 v[16];
    int tile = blockIdx.x;

    // ---- prologue: tile0 -> buf0; prefetch tile1 into regs ---------------
    if (tile < N_TILES) {
        const float4* src = (const float4*)u + (long)tile * 4096;
        #pragma unroll
        for (int j = 0; j < 8; j++) {
            int uid = tid + 256 * j;
            v[2 * j]     = src[uid * 2];
            v[2 * j + 1] = src[uid * 2 + 1];
        }
        #pragma unroll
        for (int j = 0; j < 8; j++) {
            int uid = tid + 256 * j;
            int row = uid >> 4, kk = uid & 15;
            float4 p0 = v[2 * j], p1 = v[2 * j + 1];
            __half2 h01 = __floats2half2_rn(p0.x, p0.y);
            __half2 h23 = __floats2half2_rn(p0.z, p0.w);
            __half2 h45 = __floats2half2_rn(p1.x, p1.y);
            __half2 h67 = __floats2half2_rn(p1.z, p1.w);
            int off = row * 256 + ((kk ^ (row & 7)) << 4);
            *(uint4*)(sm + UBOFF(0) + off) =
                make_uint4(*(uint32_t*)&h01, *(uint32_t*)&h23,
                           *(uint32_t*)&h45, *(uint32_t*)&h67);
        }
    }
    if (tile + grid < N_TILES) {
        const float4* src = (const float4*)u + (long)(tile + grid) * 4096;
        #pragma unroll
        for (int j = 0; j < 8; j++) {
            int uid = tid + 256 * j;
            v[2 * j]     = src[uid * 2];
            v[2 * j + 1] = src[uid * 2 + 1];
        }
    }
    __syncthreads();

    int p = 0;
    for (; tile < N_TILES; tile += grid) {
        const bool hasNext = (tile + grid) < N_TILES;
        const uint32_t ub  = UBOFF(p);
        const uint32_t ubn = UBOFF(p ^ 1);

        float acc[2][8][4];
        #pragma unroll
        for (int rf = 0; rf < 2; rf++)
            #pragma unroll
            for (int nt = 0; nt < 8; nt++)
                #pragma unroll
                for (int q = 0; q < 4; q++) acc[rf][nt][q] = 0.f;

        #pragma unroll
        for (int ks = 0; ks < 8; ks++) {
            const int k0 = ks * 16;
            uint32_t ah0[4], ah1[4];
            {
                int mk = k0 + a_kadd;
                uint32_t ad = sbase + ub +
                    (uint32_t)(a_row * 256 + (((mk >> 3) ^ r7) << 4));
                LDSM4(ah0, ad);
                LDSM4(ah1, ad + 4096u);
            }
            #pragma unroll
            for (int cg2 = 0; cg2 < 4; cg2++) {
                int n = b_n + cg2 * 16;
                int mk = k0 + b_kadd;
                uint32_t bd = sbase +
                    (uint32_t)(n * 256 + (((mk >> 3) ^ r7) << 4));
                uint32_t bh[4], bl[4];
                LDSM4(bh, bd);
                LDSM4(bl, bd + 32768u);
                const int nt = cg2 * 2;
                MMA16816H(acc[0][nt],     ah0, bh[0], bh[1]);
                MMA16816H(acc[0][nt + 1], ah0, bh[2], bh[3]);
                MMA16816H(acc[1][nt],     ah1, bh[0], bh[1]);
                MMA16816H(acc[1][nt + 1], ah1, bh[2], bh[3]);
                MMA16816H(acc[0][nt],     ah0, bl[0], bl[1]);
                MMA16816H(acc[0][nt + 1], ah0, bl[2], bl[3]);
                MMA16816H(acc[1][nt],     ah1, bl[0], bl[1]);
                MMA16816H(acc[1][nt + 1], ah1, bl[2], bl[3]);
            }
            // interleave next-tile convert/STS chunk
            if (hasNext) {
                int uid = tid + 256 * ks;
                int row = uid >> 4, kk = uid & 15;
                float4 p0 = v[2 * ks], p1 = v[2 * ks + 1];
                __half2 h01 = __floats2half2_rn(p0.x, p0.y);
                __half2 h23 = __floats2half2_rn(p0.z, p0.w);
                __half2 h45 = __floats2half2_rn(p1.x, p1.y);
                __half2 h67 = __floats2half2_rn(p1.z, p1.w);
                int off = row * 256 + ((kk ^ (row & 7)) << 4);
                *(uint4*)(sm + ubn + off) =
                    make_uint4(*(uint32_t*)&h01, *(uint32_t*)&h23,
                               *(uint32_t*)&h45, *(uint32_t*)&h67);
            }
        }

        // epilogue: fragments -> y, scaled by 2^-6
        {
            const int q = lane >> 2, s2 = (lane & 3) * 2;
            #pragma unroll
            for (int rf = 0; rf < 2; rf++) {
                long grow = (long)tile * 128 + Rw + rf * 16 + q;
                float* yp0 = y + grow * SDIM + cw * 64 + s2;
                #pragma unroll
                for (int nt = 0; nt < 8; nt++) {
                    *(float2*)(yp0 + nt * 8) =
                        make_float2(acc[rf][nt][0] * WSCALE_INV,
                                    acc[rf][nt][1] * WSCALE_INV);
                    *(float2*)(yp0 + 8 * SDIM + nt * 8) =
                        make_float2(acc[rf][nt][2] * WSCALE_INV,
                                    acc[rf][nt][3] * WSCALE_INV);
                }
            }
        }

        // prefetch tile t+2 into regs
        if (tile + 2 * grid < N_TILES) {
            const float4* src = (const float4*)u + (long)(tile + 2 * grid) * 4096;
            #pragma unroll
            for (int j = 0; j < 8; j++) {
                int uid = tid + 256 * j;
                v[2 * j]     = src[uid * 2];
                v[2 * j + 1] = src[uid * 2 + 1];
            }
        }
        __syncthreads();
        p ^= 1;
    }
}

// ===========================================================================
extern "C" void kernel_launch(void* const* d_in, const int* in_sizes, int n_in,
                              void* d_out, int out_size) {
    const float* u = (const float*)d_in[0];
    const float* A = (const float*)d_in[1];
    const float* B = (const float*)d_in[2];
    const float* C = (const float*)d_in[3];
    const float* D = (const float*)d_in[4];
    float* y = (float*)d_out;

    int sms = 0, dev = 0;
    cudaGetDevice(&dev);
    cudaDeviceGetAttribute(&sms, cudaDevAttrMultiProcessorCount, dev);
    if (sms <= 0) sms = 148;

    const int solve_smem = (16384 + 4096 + 128) * (int)sizeof(float);
    cudaFuncSetAttribute(solve_kernel, cudaFuncAttributeMaxDynamicSharedMemorySize, solve_smem);
    cudaFuncSetAttribute(gemm_kernel,  cudaFuncAttributeMaxDynamicSharedMemorySize, GSMEM_BYTES);

    solve_kernel<<<4, 256, solve_smem>>>(A, B);
    wk_kernel<<<128, 128>>>(C, D);
    gemm_kernel<<<sms, 256, GSMEM_BYTES>>>(u, y, sms);
}